// round 9
// baseline (speedup 1.0000x reference)
#include <cuda_runtime.h>
#include <cuda_fp16.h>
#include <math.h>
#include <stdint.h>

// ---------------------------------------------------------------------------
// EquiConv v8: fp16 HMMA (K=64), occupancy-3 mainloop.
//   k01_prep : W2 -> g_B fp16 chunks  +  H/silu -> g_H, seg0/1 coefs -> g_C
//   k2_main  : 64-row CTA, 256 thr, warps = (rg 0..3) x (cg 0..1), occ=3.
//              18 chunks of 128 cols, triple-buffered cp.async, one sync per
//              chunk, j-halved acc (16 regs), fragment-local contraction,
//              cg-reduction in SMEM.
// ---------------------------------------------------------------------------

#define E_ROWS 65536
#define TILE_R 64
#define NCHUNK 18
#define ASTR   72                   // fp16 elems per A row (64 + 8)
#define BSTR   72                   // fp16 elems per B row (64 + 8)
#define A_BYTES (TILE_R*ASTR*2)     // 9216
#define BS_OFF  A_BYTES
#define BBUF_B  (128*BSTR*2)        // 18432 (one chunk)
#define SMEM_TOTAL (A_BYTES + 3*BBUF_B)   // 64512

__device__ float g_H[E_ROWS * 64];
__device__ float g_C[E_ROWS * 48];
__device__ __align__(16) __half g_B[NCHUNK * 128 * 64];

// ------------------------------ asm helpers --------------------------------
__device__ __forceinline__ uint32_t smem_u32(const void* p) {
    uint32_t a;
    asm("{ .reg .u64 t; cvta.to.shared.u64 t, %1; cvt.u32.u64 %0, t; }" : "=r"(a) : "l"(p));
    return a;
}
#define LDSM4(r, a)                                                          \
    asm volatile("ldmatrix.sync.aligned.m8n8.x4.shared.b16 {%0,%1,%2,%3},[%4];" \
                 : "=r"((r)[0]), "=r"((r)[1]), "=r"((r)[2]), "=r"((r)[3]) : "r"(a))
#define MMA16816(d, a, b0, b1)                                               \
    asm volatile("mma.sync.aligned.m16n8k16.row.col.f32.f16.f16.f32 "        \
                 "{%0,%1,%2,%3},{%4,%5,%6,%7},{%8,%9},{%0,%1,%2,%3};"        \
                 : "+f"((d)[0]), "+f"((d)[1]), "+f"((d)[2]), "+f"((d)[3])    \
                 : "r"((a)[0]), "r"((a)[1]), "r"((a)[2]), "r"((a)[3]),       \
                   "r"(b0), "r"(b1))
#define CP_ASYNC16(d, s) \
    asm volatile("cp.async.cg.shared.global [%0], [%1], 16;" :: "r"(d), "l"(s))
#define CP_COMMIT()   asm volatile("cp.async.commit_group;" ::: "memory")
#define CP_WAIT1()    asm volatile("cp.async.wait_group 1;" ::: "memory")
#define CP_WAIT0()    asm volatile("cp.async.wait_group 0;" ::: "memory")

// stage one chunk (128 rows x 128B) into smem rows of stride 144B
__device__ __forceinline__ void stage_B(int chunk, uint32_t dst, int tid) {
    const char* src = (const char*)(g_B + chunk * 128 * 64);
#pragma unroll
    for (int it = 0; it < 4; it++) {
        int t16 = tid + it * 256;
        int row = t16 >> 3, c = t16 & 7;
        CP_ASYNC16(dst + row * 144 + c * 16, src + row * 128 + c * 16);
    }
}

// ---------------------------------------------------------------------------
__global__ void k01_prep(const float* __restrict__ fea_in1,
                         const float* __restrict__ fea_in2,
                         const float* __restrict__ fea_weight,
                         const float* __restrict__ W1,
                         const float* __restrict__ W2)
{
    __shared__ float W1s[64 * 64];
    __shared__ float fws[32 * 64];
    const int t  = threadIdx.x;
    const int r0 = blockIdx.x * 32;

    // ---- k0 part: W2 -> g_B fp16, chunked layout (blocks < 576) ----
    if (blockIdx.x < 576) {
        int id = blockIdx.x * 256 + t;     // covers 2304*64 exactly
        int col = id >> 6, kk = id & 63;
        int chunk = col >> 7, n = col & 127;
        g_B[(chunk * 128 + n) * 64 + kk] = __float2half(W2[kk * 2304 + col]);
    }

    // ---- k1 part ----
    for (int idx = t; idx < 64 * 64; idx += 256) W1s[idx] = W1[idx];
    for (int idx = t; idx < 32 * 64; idx += 256) fws[idx] = fea_weight[r0 * 64 + idx];
    __syncthreads();

    const int rl = t >> 3, l8 = t & 7, grow = r0 + rl;
    float acc[8];
#pragma unroll
    for (int jj = 0; jj < 8; jj++) acc[jj] = 0.f;
#pragma unroll 8
    for (int k = 0; k < 64; k++) {
        const float fv = fws[rl * 64 + k];
#pragma unroll
        for (int jj = 0; jj < 8; jj++) acc[jj] += fv * W1s[k * 64 + jj * 8 + l8];
    }
#pragma unroll
    for (int jj = 0; jj < 8; jj++) {
        const float z = acc[jj] * 0.125f;
        const float s = z / (1.f + expf(-z));
        g_H[grow * 64 + jj * 8 + l8] = 1.679f * s * 0.125f;   // fold W2's /8
    }

    const float x20  = fea_in2[grow * 4 + 0];
    const float x21a = fea_in2[grow * 4 + 1];
    const float x21b = fea_in2[grow * 4 + 2];
    const float x21c = fea_in2[grow * 4 + 3];
    for (int u = l8; u < 32; u += 8)
        g_C[grow * 48 + u] = 0.125f * x20 * fea_in1[grow * 80 + u];      // pw00
    for (int u = l8; u < 16; u += 8) {
        const float* p = fea_in1 + grow * 80 + 32 + u * 3;
        const float b = p[0] * x21a + p[1] * x21b + p[2] * x21c;
        g_C[grow * 48 + 32 + u] = 0.10206207261596575f * b;              // 1/sqrt(96)
    }
}

// ---------------------------------------------------------------------------
// contraction of one j-half (jj = 0..3, global j = jh*4+jj)
__device__ __forceinline__ void contract_half(
    int m, int jh, const float acc[4][4], float* o0, float* sA, float* qA,
    int rbase, int cg, const float* __restrict__ fea_in1)
{
    if (m < 12) {
        const int ubase = (m < 8 ? m * 4 : 32 + (m - 8) * 4) + cg * 2 + jh;
#pragma unroll
        for (int rh = 0; rh < 2; rh++) {
            const int row = rbase + rh * 8;
            const float c = g_C[row * 48 + ubase];
#pragma unroll
            for (int jj = 0; jj < 4; jj++) {
                const int s = (rh * 4 + jj) * 2;
                o0[s]     = fmaf(c, acc[jj][rh * 2],     o0[s]);
                o0[s + 1] = fmaf(c, acc[jj][rh * 2 + 1], o0[s + 1]);
            }
        }
    } else if (m < 16) {
        const int u0 = (m - 12) * 8 + cg * 4 + jh * 2;
#pragma unroll
        for (int rh = 0; rh < 2; rh++) {
            const int row = rbase + rh * 8;
            const float* xr = fea_in1 + row * 80 + u0;
#pragma unroll
            for (int jj = 0; jj < 4; jj++) {
                const float cu = xr[jj >> 1];
                const int s = rh * 4 + (jj & 1) * 2;
                sA[s]     = fmaf(cu, acc[jj][rh * 2],     sA[s]);
                sA[s + 1] = fmaf(cu, acc[jj][rh * 2 + 1], sA[s + 1]);
            }
        }
    } else {
        const int u0 = (m - 16) * 8 + cg * 4 + jh * 2;
#pragma unroll
        for (int rh = 0; rh < 2; rh++) {
            const int row = rbase + rh * 8;
            const float* xr = fea_in1 + row * 80 + 32 + 3 * u0;
#pragma unroll
            for (int jj = 0; jj < 4; jj++) {
                const int s = (rh * 4 + (jj & 1) * 2) * 3;
#pragma unroll
                for (int k = 0; k < 3; k++) {
                    const float cu = xr[3 * (jj >> 1) + k];
                    qA[s + k]     = fmaf(cu, acc[jj][rh * 2],     qA[s + k]);
                    qA[s + 3 + k] = fmaf(cu, acc[jj][rh * 2 + 1], qA[s + 3 + k]);
                }
            }
        }
    }
}

// ---------------------------------------------------------------------------
__global__ __launch_bounds__(256, 3)
void k2_main(const float* __restrict__ fea_in1,
             const float* __restrict__ fea_in2,
             float* __restrict__ out)
{
    extern __shared__ __align__(16) char smem[];
    const uint32_t sbase = smem_u32(smem);
    const int tid = threadIdx.x, wid = tid >> 5, lane = tid & 31;
    const int rg = wid >> 1, cg = wid & 1;
    const int r0 = blockIdx.x * TILE_R;

    // ---- build A tile: [64 rows][64 k] fp16, stride 72 ----
    __half* As = (__half*)smem;
    for (int idx = tid; idx < TILE_R * 64; idx += 256) {
        const int r = idx >> 6, j = idx & 63;
        As[r * ASTR + j] = __float2half(g_H[(r0 + r) * 64 + j]);
    }
    stage_B(0, sbase + BS_OFF, tid);              CP_COMMIT();
    stage_B(1, sbase + BS_OFF + BBUF_B, tid);     CP_COMMIT();

    // ldmatrix address groups
    const int gp = lane >> 3, lr = lane & 7;
    const uint32_t aBase = sbase + (uint32_t)(((rg * 16 + 8 * (gp & 1) + lr) * ASTR
                                               + 8 * (gp >> 1)) * 2);
    uint32_t bOff[4];
#pragma unroll
    for (int p = 0; p < 4; p++)
        bOff[p] = (uint32_t)(((cg * 64 + 16 * p + 8 * (gp >> 1) + lr) * BSTR
                              + 8 * (gp & 1)) * 2);

    // persistent per-thread partial accumulators
    float o0[16], sA[8], qA[24];
#pragma unroll
    for (int i = 0; i < 16; i++) o0[i] = 0.f;
#pragma unroll
    for (int i = 0; i < 8; i++) sA[i] = 0.f;
#pragma unroll
    for (int i = 0; i < 24; i++) qA[i] = 0.f;

    const int rowq = lane >> 2;
    const int rbase = r0 + rg * 16 + rowq;     // + rh*8
    const int q2 = (lane & 3) * 2;

#pragma unroll 1
    for (int m = 0; m < NCHUNK; m++) {
        if (m < NCHUNK - 1) { CP_WAIT1(); } else { CP_WAIT0(); }
        __syncthreads();
        // stage chunk m+2 into buf[(m+2)%3]; its previous readers (chunk m-1)
        // finished before the sync above.
        if (m + 2 < NCHUNK) {
            stage_B(m + 2, sbase + BS_OFF + (uint32_t)((m + 2) % 3) * BBUF_B, tid);
            CP_COMMIT();
        }
        const uint32_t sbB = sbase + BS_OFF + (uint32_t)(m % 3) * BBUF_B;

#pragma unroll
        for (int jh = 0; jh < 2; jh++) {
            float acc[4][4];
#pragma unroll
            for (int jj = 0; jj < 4; jj++)
#pragma unroll
                for (int c = 0; c < 4; c++) acc[jj][c] = 0.f;

#pragma unroll
            for (int ksb = 0; ksb < 4; ksb++) {
                uint32_t a[4], r[4], r2[4];
                LDSM4(a, aBase + ksb * 32);
                LDSM4(r,  sbB + bOff[2 * jh]     + ksb * 32);
                LDSM4(r2, sbB + bOff[2 * jh + 1] + ksb * 32);
                MMA16816(acc[0], a, r[0],  r[1]);
                MMA16816(acc[1], a, r[2],  r[3]);
                MMA16816(acc[2], a, r2[0], r2[1]);
                MMA16816(acc[3], a, r2[2], r2[3]);
            }
            contract_half(m, jh, acc, o0, sA, qA, rbase, cg, fea_in1);
        }
    }

    // ---- cross-cg reduction (cg=1 partials -> cg=0), reuse B area ----
    __syncthreads();
    float* red = (float*)(smem + BS_OFF);      // 128 thr * 48 f = 24576 B
    const int half_id = rg * 32 + lane;
    if (cg == 1) {
        float* dst = red + half_id * 48;
#pragma unroll
        for (int i = 0; i < 16; i++) dst[i] = o0[i];
#pragma unroll
        for (int i = 0; i < 8; i++) dst[16 + i] = sA[i];
#pragma unroll
        for (int i = 0; i < 24; i++) dst[24 + i] = qA[i];
    }
    __syncthreads();
    if (cg == 0) {
        const float* src = red + half_id * 48;
#pragma unroll
        for (int i = 0; i < 16; i++) o0[i] += src[i];
#pragma unroll
        for (int i = 0; i < 8; i++) sA[i] += src[16 + i];
#pragma unroll
        for (int i = 0; i < 24; i++) qA[i] += src[24 + i];

        // ---- epilogue ----
        const float c011 = 0.125f;                 // pw011/sqrt(3)
        const float c101 = 0.17677669529663687f;   // pw101/sqrt(3)
#pragma unroll
        for (int rh = 0; rh < 2; rh++) {
            const int row = rbase + rh * 8;
            float* orow = out + row * 80;
            const int s = rh * 4;
#pragma unroll
            for (int jm = 0; jm < 4; jm++) {
                orow[8 * jm + q2]     = o0[(s + jm) * 2];
                orow[8 * jm + q2 + 1] = o0[(s + jm) * 2 + 1];
            }
            const float x20  = fea_in2[row * 4 + 0];
            const float x21a = fea_in2[row * 4 + 1];
            const float x21b = fea_in2[row * 4 + 2];
            const float x21c = fea_in2[row * 4 + 3];
#pragma unroll
            for (int slot = 0; slot < 4; slot++) {
                const int w = 8 * (slot >> 1) + q2 + (slot & 1);
                const float sv = sA[s + slot];
                orow[32 + 3 * w + 0] = c011 * x21a * sv + c101 * x20 * qA[(s + slot) * 3 + 0];
                orow[32 + 3 * w + 1] = c011 * x21b * sv + c101 * x20 * qA[(s + slot) * 3 + 1];
                orow[32 + 3 * w + 2] = c011 * x21c * sv + c101 * x20 * qA[(s + slot) * 3 + 2];
            }
        }
    }
}

// ---------------------------------------------------------------------------
extern "C" void kernel_launch(void* const* d_in, const int* in_sizes, int n_in,
                              void* d_out, int out_size)
{
    const float* fea_in1    = (const float*)d_in[0];
    const float* fea_in2    = (const float*)d_in[1];
    const float* fea_weight = (const float*)d_in[2];
    const float* W1         = (const float*)d_in[3];
    const float* W2         = (const float*)d_in[4];
    float* out = (float*)d_out;

    cudaFuncSetAttribute(k2_main, cudaFuncAttributeMaxDynamicSharedMemorySize, SMEM_TOTAL);

    k01_prep<<<E_ROWS / 32, 256>>>(fea_in1, fea_in2, fea_weight, W1, W2);
    k2_main<<<E_ROWS / TILE_R, 256, SMEM_TOTAL>>>(fea_in1, fea_in2, out);
}